// round 13
// baseline (speedup 1.0000x reference)
#include <cuda_runtime.h>
#include <cuda_fp16.h>
#include <cstdint>

#define N 8192
#define D 256
#define KE 256
#define BM 128
#define BN 256
#define BK 32
#define THREADS 512
#define ITERS (KE / BK)     // 8
#define NBLOCKS 1056        // (I,J): I in [0, 2J+2), J in [0,32)
#define NSTAGE 4
#define LDA 40
#define A_BYTES (BM * LDA * 2)              // 10240
#define B_BYTES (BN * LDA * 2)              // 20480
#define STAGE_BYTES (A_BYTES + B_BYTES)     // 30720
#define RING_BYTES (NSTAGE * STAGE_BYTES)   // 122880

// ---------------------------------------------------------------------------
__device__ __half g_hi[N * D];
__device__ float g_norms[N];
__device__ int   g_maxpos_i[N];          // encoded floats, INT_MIN = none
__device__ int   g_minneg_i[N];          // encoded floats, INT_MAX = none

__device__ __forceinline__ int f2i(float f) {
    int i = __float_as_int(f);
    return i >= 0 ? i : (i ^ 0x7fffffff);
}
__device__ __forceinline__ float i2f(int i) {
    return __int_as_float(i >= 0 ? i : (i ^ 0x7fffffff));
}
__device__ __forceinline__ uint32_t smem_u32(const void* p) {
    uint32_t a;
    asm("{ .reg .u64 t; cvta.to.shared.u64 t, %1; cvt.u32.u64 %0, t; }"
        : "=r"(a) : "l"(p));
    return a;
}
__device__ __forceinline__ void cp16(uint32_t s, const void* g) {
    asm volatile("cp.async.cg.shared.global [%0], [%1], 16;\n"
                 :: "r"(s), "l"(g) : "memory");
}
#define CP_COMMIT() asm volatile("cp.async.commit_group;" ::: "memory")
#define CP_WAIT(n)  asm volatile("cp.async.wait_group %0;" :: "n"(n) : "memory")

#define LDSM_X4(r0, r1, r2, r3, a)                                            \
    asm volatile("ldmatrix.sync.aligned.m8n8.x4.shared.b16 {%0,%1,%2,%3}, [%4];" \
                 : "=r"(r0), "=r"(r1), "=r"(r2), "=r"(r3) : "r"(a))

#define MMA_F16(c, a0, a1, a2, a3, b0, b1)                                    \
    asm volatile(                                                             \
        "mma.sync.aligned.m16n8k16.row.col.f32.f16.f16.f32 "                  \
        "{%0,%1,%2,%3}, {%4,%5,%6,%7}, {%8,%9}, {%0,%1,%2,%3};"               \
        : "+f"((c)[0]), "+f"((c)[1]), "+f"((c)[2]), "+f"((c)[3])              \
        : "r"(a0), "r"(a1), "r"(a2), "r"(a3), "r"(b0), "r"(b1))

// ---------------------------------------------------------------------------
// Prep (fused): warp per row — fp16 convert + exact fp32 norm + init
// ---------------------------------------------------------------------------
__global__ void prep_kernel(const float* __restrict__ feat) {
    int gtid = blockIdx.x * blockDim.x + threadIdx.x;
    int row = gtid >> 5;
    int lane = gtid & 31;
    if (row >= N) return;
    const float4* f = reinterpret_cast<const float4*>(feat + (size_t)row * D);
    float4 v0 = f[lane * 2];
    float4 v1 = f[lane * 2 + 1];
    float s = v0.x * v0.x + v0.y * v0.y + v0.z * v0.z + v0.w * v0.w
            + v1.x * v1.x + v1.y * v1.y + v1.z * v1.z + v1.w * v1.w;
    __half h[8];
    h[0] = __float2half_rn(v0.x); h[1] = __float2half_rn(v0.y);
    h[2] = __float2half_rn(v0.z); h[3] = __float2half_rn(v0.w);
    h[4] = __float2half_rn(v1.x); h[5] = __float2half_rn(v1.y);
    h[6] = __float2half_rn(v1.z); h[7] = __float2half_rn(v1.w);
    *reinterpret_cast<uint4*>(g_hi + (size_t)row * D + lane * 8) =
        *reinterpret_cast<uint4*>(h);
#pragma unroll
    for (int m = 16; m > 0; m >>= 1) s += __shfl_xor_sync(0xffffffffu, s, m);
    if (lane == 0) {
        g_norms[row] = s;
        g_maxpos_i[row] = INT_MIN;
        g_minneg_i[row] = INT_MAX;
    }
}

// ---------------------------------------------------------------------------
// Main: 128x256 HMMA tile, 512 threads, 4-stage ring, 1 sync/iter.
// Tile set {(I,J): I <= 2J+1} covers all unordered pairs (row-mine I rows,
// col-mine J cols); diagonal-straddling tiles (I>>1 == J) exclude self-pairs.
// ---------------------------------------------------------------------------
__global__ __launch_bounds__(THREADS, 1)
void gram_kernel(const int* __restrict__ labels) {
    extern __shared__ char ring[];
    __shared__ int   sColLab[BN];
    __shared__ float sColNorm[BN];
    __shared__ int   sRowLab[BM];
    __shared__ float sRowNorm[BM];
    __shared__ int   sMp[BM],  sMn[BM];
    __shared__ int   sMp2[BN], sMn2[BN];

    // decode (I, J): count per J is 2J+2
    int t = blockIdx.x;
    int J = 0;
    while (t >= 2 * J + 2) { t -= 2 * J + 2; J++; }
    const int I = t;
    const bool hasdiag = ((I >> 1) == J);
    const int rowBase = I * BM;
    const int colBase = J * BN;

    const int tid = threadIdx.x;
    const int lane = tid & 31;
    const int wid = tid >> 5;
    const int warp_m = wid >> 3;          // 0..1  (64 rows each)
    const int warp_n = wid & 7;           // 0..7  (32 cols each)

    if (tid < BN) {
        sColLab[tid]  = labels[colBase + tid];
        sColNorm[tid] = g_norms[colBase + tid];
        sMp2[tid] = INT_MIN; sMn2[tid] = INT_MAX;
    }
    if (tid < BM) {
        sRowLab[tid]  = labels[rowBase + tid];
        sRowNorm[tid] = g_norms[rowBase + tid];
        sMp[tid] = INT_MIN;  sMn[tid] = INT_MAX;
    }

    const uint32_t ringBase = smem_u32(ring);
    const uint32_t aOff = ((warp_m * 64 + (lane & 15)) * LDA + (lane >> 4) * 8) * 2;
    const uint32_t bOff = ((warp_n * 32 + (lane & 7) + ((lane >> 4) & 1) * 8) * LDA
                          + ((lane >> 3) & 1) * 8) * 2;

    const __half* ga = g_hi + (size_t)rowBase * D;
    const __half* gb = g_hi + (size_t)colBase * D;

    auto load_stage = [&](int kt, int stg) {
        const uint32_t sA = ringBase + stg * STAGE_BYTES;
        const uint32_t sB = sA + A_BYTES;
        const int k0 = kt * BK;
        {   // A: 512 chunks of 16B, one per thread
            int r = tid >> 2, c = tid & 3;
            cp16(sA + (r * LDA + c * 8) * 2, ga + (size_t)r * D + k0 + c * 8);
        }
#pragma unroll
        for (int i = 0; i < 2; i++) {     // B: 1024 chunks, two per thread
            int idx = tid + i * THREADS;
            int r = idx >> 2, c = idx & 3;
            cp16(sB + (r * LDA + c * 8) * 2, gb + (size_t)r * D + k0 + c * 8);
        }
        CP_COMMIT();
    };

    float acc[4][4][4];
#pragma unroll
    for (int i = 0; i < 4; i++)
#pragma unroll
        for (int j = 0; j < 4; j++)
#pragma unroll
            for (int e = 0; e < 4; e++) acc[i][j][e] = 0.f;

    load_stage(0, 0);
    load_stage(1, 1);
    load_stage(2, 2);

    for (int it = 0; it < ITERS; ++it) {
        CP_WAIT(2);
        __syncthreads();
        // slot (it+3)&3's last readers were iter it-1; all passed the sync
        if (it + 3 < ITERS) load_stage(it + 3, (it + 3) & (NSTAGE - 1));
        else CP_COMMIT();   // empty group keeps wait accounting exact

        const uint32_t sA = ringBase + (it & (NSTAGE - 1)) * STAGE_BYTES;
        const uint32_t sB = sA + A_BYTES;
#pragma unroll
        for (int ks = 0; ks < 2; ks++) {
            uint32_t aF[4][4], bF[2][4];
#pragma unroll
            for (int mt = 0; mt < 4; mt++)
                LDSM_X4(aF[mt][0], aF[mt][1], aF[mt][2], aF[mt][3],
                        sA + aOff + mt * (16 * LDA * 2) + ks * 32);
#pragma unroll
            for (int ng = 0; ng < 2; ng++)
                LDSM_X4(bF[ng][0], bF[ng][1], bF[ng][2], bF[ng][3],
                        sB + bOff + ng * (16 * LDA * 2) + ks * 32);
#pragma unroll
            for (int mt = 0; mt < 4; mt++) {
#pragma unroll
                for (int nt = 0; nt < 4; nt++) {
                    const int ng = nt >> 1;
                    const int hi = (nt & 1) << 1;
                    MMA_F16(acc[mt][nt], aF[mt][0], aF[mt][1], aF[mt][2],
                            aF[mt][3], bF[ng][hi], bF[ng][hi + 1]);
                }
            }
        }
    }

    // ---- epilogue ----
    {
        float cn8[8]; int clab8[8], cc8[8];
#pragma unroll
        for (int nt = 0; nt < 4; nt++)
#pragma unroll
            for (int e = 0; e < 2; e++) {
                int cc = warp_n * 32 + nt * 8 + (lane & 3) * 2 + e;
                cc8[nt * 2 + e] = cc;
                cn8[nt * 2 + e] = sColNorm[cc];
                clab8[nt * 2 + e] = sColLab[cc];
            }
        int rl8[8]; float rn8[8]; int rr8[8];
#pragma unroll
        for (int mt = 0; mt < 4; mt++)
#pragma unroll
            for (int h = 0; h < 2; h++) {
                int rr = warp_m * 64 + mt * 16 + (lane >> 2) + h * 8;
                rr8[mt * 2 + h] = rr;
                rl8[mt * 2 + h] = sRowLab[rr];
                rn8[mt * 2 + h] = sRowNorm[rr];
            }

        // --- row-wise mining: v = cn - 2*dot ---
        float mp[8], mn[8];
#pragma unroll
        for (int i = 0; i < 8; i++) { mp[i] = -3.0e38f; mn[i] = 3.0e38f; }
#pragma unroll
        for (int mt = 0; mt < 4; mt++)
#pragma unroll
            for (int h = 0; h < 2; h++) {
                const int ri = mt * 2 + h;
#pragma unroll
                for (int nt = 0; nt < 4; nt++)
#pragma unroll
                    for (int e = 0; e < 2; e++) {
                        const int ci = nt * 2 + e;
                        float v = fmaf(-2.f, acc[mt][nt][h * 2 + e], cn8[ci]);
                        bool same = (rl8[ri] == clab8[ci]);
                        bool self = hasdiag &&
                            (rowBase + rr8[ri] == colBase + cc8[ci]);
                        if (same) {
                            if (!self) mp[ri] = fmaxf(mp[ri], v);
                        } else {
                            mn[ri] = fminf(mn[ri], v);
                        }
                    }
            }
#pragma unroll
        for (int i = 0; i < 8; i++) {
#pragma unroll
            for (int m = 1; m < 4; m <<= 1) {
                mp[i] = fmaxf(mp[i], __shfl_xor_sync(0xffffffffu, mp[i], m));
                mn[i] = fminf(mn[i], __shfl_xor_sync(0xffffffffu, mn[i], m));
            }
        }
        if ((lane & 3) == 0) {
#pragma unroll
            for (int i = 0; i < 8; i++) {
                if (mp[i] > -2.9e38f) atomicMax(&sMp[rr8[i]], f2i(mp[i]));
                if (mn[i] <  2.9e38f) atomicMin(&sMn[rr8[i]], f2i(mn[i]));
            }
        }

        // --- column-wise mining (all tiles): v' = rn - 2*dot ---
        {
            float mpc[8], mnc[8];
#pragma unroll
            for (int i = 0; i < 8; i++) { mpc[i] = -3.0e38f; mnc[i] = 3.0e38f; }
#pragma unroll
            for (int nt = 0; nt < 4; nt++)
#pragma unroll
                for (int e = 0; e < 2; e++) {
                    const int ci = nt * 2 + e;
#pragma unroll
                    for (int mt = 0; mt < 4; mt++)
#pragma unroll
                        for (int h = 0; h < 2; h++) {
                            const int ri = mt * 2 + h;
                            float v = fmaf(-2.f, acc[mt][nt][h * 2 + e], rn8[ri]);
                            bool same = (rl8[ri] == clab8[ci]);
                            bool self = hasdiag &&
                                (rowBase + rr8[ri] == colBase + cc8[ci]);
                            if (same) {
                                if (!self) mpc[ci] = fmaxf(mpc[ci], v);
                            } else {
                                mnc[ci] = fminf(mnc[ci], v);
                            }
                        }
                }
#pragma unroll
            for (int i = 0; i < 8; i++) {
#pragma unroll
                for (int m = 4; m < 32; m <<= 1) {
                    mpc[i] = fmaxf(mpc[i], __shfl_xor_sync(0xffffffffu, mpc[i], m));
                    mnc[i] = fminf(mnc[i], __shfl_xor_sync(0xffffffffu, mnc[i], m));
                }
            }
            if (lane < 4) {
#pragma unroll
                for (int nt = 0; nt < 4; nt++)
#pragma unroll
                    for (int e = 0; e < 2; e++) {
                        int cc = warp_n * 32 + nt * 8 + lane * 2 + e;
                        const int ci = nt * 2 + e;
                        if (mpc[ci] > -2.9e38f) atomicMax(&sMp2[cc], f2i(mpc[ci]));
                        if (mnc[ci] <  2.9e38f) atomicMin(&sMn2[cc], f2i(mnc[ci]));
                    }
            }
        }
    }
    __syncthreads();
    if (tid < BM) {
        if (sMp[tid] != INT_MIN) atomicMax(&g_maxpos_i[rowBase + tid], sMp[tid]);
        if (sMn[tid] != INT_MAX) atomicMin(&g_minneg_i[rowBase + tid], sMn[tid]);
    }
    if (tid < BN) {
        if (sMp2[tid] != INT_MIN) atomicMax(&g_maxpos_i[colBase + tid], sMp2[tid]);
        if (sMn2[tid] != INT_MAX) atomicMin(&g_minneg_i[colBase + tid], sMn2[tid]);
    }
}

// ---------------------------------------------------------------------------
// Finalize (single block, 1024 threads): per-row sqrt + margin, exact mean
// ---------------------------------------------------------------------------
__global__ void finalize_kernel(float* __restrict__ out) {
    __shared__ float ssum[1024];
    int t = threadIdx.x;
    float s = 0.f;
    for (int r = t; r < N; r += 1024) {
        float rn = g_norms[r];
        int ep = g_maxpos_i[r];
        int en = g_minneg_i[r];
        float ap = (ep == INT_MIN) ? 0.f : sqrtf(fmaxf(rn + i2f(ep), 0.f));
        float an = (en == INT_MAX) ? 1e6f : sqrtf(fmaxf(rn + i2f(en), 0.f));
        s += fmaxf(0.f, 0.3f + ap - an);
    }
    ssum[t] = s;
    __syncthreads();
    for (int off = 512; off > 0; off >>= 1) {
        if (t < off) ssum[t] += ssum[t + off];
        __syncthreads();
    }
    if (t == 0) out[0] = ssum[0] / (float)N;
}

// ---------------------------------------------------------------------------
extern "C" void kernel_launch(void* const* d_in, const int* in_sizes, int n_in,
                              void* d_out, int out_size) {
    const float* feat = (const float*)d_in[0];
    const int* labels = (const int*)d_in[1];
    float* out = (float*)d_out;

    cudaFuncSetAttribute(gram_kernel,
                         cudaFuncAttributeMaxDynamicSharedMemorySize, RING_BYTES);

    prep_kernel<<<(N * 32 + 255) / 256, 256>>>(feat);
    gram_kernel<<<NBLOCKS, THREADS, RING_BYTES>>>(labels);
    finalize_kernel<<<1, 1024>>>(out);
}

// round 14
// speedup vs baseline: 1.2286x; 1.2286x over previous
#include <cuda_runtime.h>
#include <cuda_fp16.h>
#include <cstdint>

#define N 8192
#define D 256
#define KE 256              // pure fp16 hi.hi
#define BM 128
#define BN 128
#define BK 32
#define THREADS 256
#define ITERS (KE / BK)                     // 8
#define NTILE (N / BM)                      // 64
#define NBLOCKS (NTILE * (NTILE + 1) / 2)   // 2080
#define NSTAGE 4
#define LDA 40
#define A_BYTES (BM * LDA * 2)              // 10240
#define B_BYTES (BN * LDA * 2)              // 10240
#define STAGE_BYTES (A_BYTES + B_BYTES)     // 20480
#define RING_BYTES (NSTAGE * STAGE_BYTES)   // 81920

// ---------------------------------------------------------------------------
__device__ __half g_hi[N * D];
__device__ float g_norms[N];
__device__ int   g_maxpos_i[N];          // encoded floats, INT_MIN = none
__device__ int   g_minneg_i[N];          // encoded floats, INT_MAX = none

__device__ __forceinline__ int f2i(float f) {
    int i = __float_as_int(f);
    return i >= 0 ? i : (i ^ 0x7fffffff);
}
__device__ __forceinline__ float i2f(int i) {
    return __int_as_float(i >= 0 ? i : (i ^ 0x7fffffff));
}
__device__ __forceinline__ uint32_t smem_u32(const void* p) {
    uint32_t a;
    asm("{ .reg .u64 t; cvta.to.shared.u64 t, %1; cvt.u32.u64 %0, t; }"
        : "=r"(a) : "l"(p));
    return a;
}
__device__ __forceinline__ void cp16(uint32_t s, const void* g) {
    asm volatile("cp.async.cg.shared.global [%0], [%1], 16;\n"
                 :: "r"(s), "l"(g) : "memory");
}
#define CP_COMMIT() asm volatile("cp.async.commit_group;" ::: "memory")
#define CP_WAIT(n)  asm volatile("cp.async.wait_group %0;" :: "n"(n) : "memory")

#define LDSM_X4(r0, r1, r2, r3, a)                                            \
    asm volatile("ldmatrix.sync.aligned.m8n8.x4.shared.b16 {%0,%1,%2,%3}, [%4];" \
                 : "=r"(r0), "=r"(r1), "=r"(r2), "=r"(r3) : "r"(a))

#define MMA_F16(c, a0, a1, a2, a3, b0, b1)                                    \
    asm volatile(                                                             \
        "mma.sync.aligned.m16n8k16.row.col.f32.f16.f16.f32 "                  \
        "{%0,%1,%2,%3}, {%4,%5,%6,%7}, {%8,%9}, {%0,%1,%2,%3};"               \
        : "+f"((c)[0]), "+f"((c)[1]), "+f"((c)[2]), "+f"((c)[3])              \
        : "r"(a0), "r"(a1), "r"(a2), "r"(a3), "r"(b0), "r"(b1))

// ---------------------------------------------------------------------------
// Prep (fused): warp per row — fp16 convert + exact fp32 norm + init
// ---------------------------------------------------------------------------
__global__ void prep_kernel(const float* __restrict__ feat) {
    int gtid = blockIdx.x * blockDim.x + threadIdx.x;
    int row = gtid >> 5;
    int lane = gtid & 31;
    if (row >= N) return;
    const float4* f = reinterpret_cast<const float4*>(feat + (size_t)row * D);
    float4 v0 = f[lane * 2];
    float4 v1 = f[lane * 2 + 1];
    float s = v0.x * v0.x + v0.y * v0.y + v0.z * v0.z + v0.w * v0.w
            + v1.x * v1.x + v1.y * v1.y + v1.z * v1.z + v1.w * v1.w;
    __half h[8];
    h[0] = __float2half_rn(v0.x); h[1] = __float2half_rn(v0.y);
    h[2] = __float2half_rn(v0.z); h[3] = __float2half_rn(v0.w);
    h[4] = __float2half_rn(v1.x); h[5] = __float2half_rn(v1.y);
    h[6] = __float2half_rn(v1.z); h[7] = __float2half_rn(v1.w);
    *reinterpret_cast<uint4*>(g_hi + (size_t)row * D + lane * 8) =
        *reinterpret_cast<uint4*>(h);
#pragma unroll
    for (int m = 16; m > 0; m >>= 1) s += __shfl_xor_sync(0xffffffffu, s, m);
    if (lane == 0) {
        g_norms[row] = s;
        g_maxpos_i[row] = INT_MIN;
        g_minneg_i[row] = INT_MAX;
    }
}

// ---------------------------------------------------------------------------
// Main: symmetric HMMA Gram (128x128, occ 2), 4-stage ring, 1 sync/iter
// ---------------------------------------------------------------------------
__global__ __launch_bounds__(THREADS, 2)
void gram_kernel(const int* __restrict__ labels) {
    extern __shared__ char ring[];
    __shared__ int   sColLab[BN];
    __shared__ float sColNorm[BN];
    __shared__ int   sRowLab[BM];
    __shared__ float sRowNorm[BM];
    __shared__ int   sMp[BM],  sMn[BM];
    __shared__ int   sMp2[BN], sMn2[BN];

    // decode upper-triangular tile pair (I <= J)
    int t = blockIdx.x;
    int I = 0;
    while (t >= NTILE - I) { t -= NTILE - I; I++; }
    const int J = I + t;
    const bool offdiag = (I != J);
    const int rowBase = I * BM;
    const int colBase = J * BN;

    const int tid = threadIdx.x;
    const int lane = tid & 31;
    const int wid = tid >> 5;
    const int warp_m = wid >> 2;          // 0..1  (64 rows each)
    const int warp_n = wid & 3;           // 0..3  (32 cols each)

    if (tid < BM) {
        sColLab[tid]  = labels[colBase + tid];
        sColNorm[tid] = g_norms[colBase + tid];
        sRowLab[tid]  = labels[rowBase + tid];
        sRowNorm[tid] = g_norms[rowBase + tid];
        sMp[tid] = INT_MIN;  sMn[tid] = INT_MAX;
        sMp2[tid] = INT_MIN; sMn2[tid] = INT_MAX;
    }

    const uint32_t ringBase = smem_u32(ring);
    const uint32_t aOff = ((warp_m * 64 + (lane & 15)) * LDA + (lane >> 4) * 8) * 2;
    const uint32_t bOff = ((warp_n * 32 + (lane & 7) + ((lane >> 4) & 1) * 8) * LDA
                          + ((lane >> 3) & 1) * 8) * 2;

    const __half* ga = g_hi + (size_t)rowBase * D;
    const __half* gb = g_hi + (size_t)colBase * D;

    auto load_stage = [&](int kt, int stg) {
        const uint32_t sA = ringBase + stg * STAGE_BYTES;
        const uint32_t sB = sA + A_BYTES;
        const int k0 = kt * BK;
#pragma unroll
        for (int i = 0; i < 2; i++) {
            int idx = tid + i * THREADS;
            int r = idx >> 2, c = idx & 3;
            cp16(sA + (r * LDA + c * 8) * 2, ga + (size_t)r * D + k0 + c * 8);
        }
#pragma unroll
        for (int i = 0; i < 2; i++) {
            int idx = tid + i * THREADS;
            int r = idx >> 2, c = idx & 3;
            cp16(sB + (r * LDA + c * 8) * 2, gb + (size_t)r * D + k0 + c * 8);
        }
        CP_COMMIT();
    };

    float acc[4][4][4];
#pragma unroll
    for (int i = 0; i < 4; i++)
#pragma unroll
        for (int j = 0; j < 4; j++)
#pragma unroll
            for (int e = 0; e < 4; e++) acc[i][j][e] = 0.f;

    load_stage(0, 0);
    load_stage(1, 1);
    load_stage(2, 2);

    for (int it = 0; it < ITERS; ++it) {
        CP_WAIT(2);
        __syncthreads();
        // slot (it+3)&3's last readers ran in iter it-1; all passed the sync
        if (it + 3 < ITERS) load_stage(it + 3, (it + 3) & (NSTAGE - 1));
        else CP_COMMIT();   // empty group keeps wait_group accounting exact

        const uint32_t sA = ringBase + (it & (NSTAGE - 1)) * STAGE_BYTES;
        const uint32_t sB = sA + A_BYTES;
#pragma unroll
        for (int ks = 0; ks < 2; ks++) {
            uint32_t aF[4][4], bF[2][4];
#pragma unroll
            for (int mt = 0; mt < 4; mt++)
                LDSM_X4(aF[mt][0], aF[mt][1], aF[mt][2], aF[mt][3],
                        sA + aOff + mt * (16 * LDA * 2) + ks * 32);
#pragma unroll
            for (int ng = 0; ng < 2; ng++)
                LDSM_X4(bF[ng][0], bF[ng][1], bF[ng][2], bF[ng][3],
                        sB + bOff + ng * (16 * LDA * 2) + ks * 32);
#pragma unroll
            for (int mt = 0; mt < 4; mt++) {
#pragma unroll
                for (int nt = 0; nt < 4; nt++) {
                    const int ng = nt >> 1;
                    const int hi = (nt & 1) << 1;
                    MMA_F16(acc[mt][nt], aF[mt][0], aF[mt][1], aF[mt][2],
                            aF[mt][3], bF[ng][hi], bF[ng][hi + 1]);
                }
            }
        }
    }

    // ---- epilogue ----
    {
        float cn8[8]; int clab8[8];
#pragma unroll
        for (int nt = 0; nt < 4; nt++)
#pragma unroll
            for (int e = 0; e < 2; e++) {
                int cc = warp_n * 32 + nt * 8 + (lane & 3) * 2 + e;
                cn8[nt * 2 + e] = sColNorm[cc];
                clab8[nt * 2 + e] = sColLab[cc];
            }
        int rl8[8]; float rn8[8]; int rr8[8];
#pragma unroll
        for (int mt = 0; mt < 4; mt++)
#pragma unroll
            for (int h = 0; h < 2; h++) {
                int rr = warp_m * 64 + mt * 16 + (lane >> 2) + h * 8;
                rr8[mt * 2 + h] = rr;
                rl8[mt * 2 + h] = sRowLab[rr];
                rn8[mt * 2 + h] = sRowNorm[rr];
            }

        // --- row-wise mining: v = cn - 2*dot ---
        float mp[8], mn[8];
#pragma unroll
        for (int i = 0; i < 8; i++) { mp[i] = -3.0e38f; mn[i] = 3.0e38f; }
#pragma unroll
        for (int mt = 0; mt < 4; mt++)
#pragma unroll
            for (int h = 0; h < 2; h++) {
                const int ri = mt * 2 + h;
#pragma unroll
                for (int nt = 0; nt < 4; nt++)
#pragma unroll
                    for (int e = 0; e < 2; e++) {
                        const int ci = nt * 2 + e;
                        float v = fmaf(-2.f, acc[mt][nt][h * 2 + e], cn8[ci]);
                        bool same = (rl8[ri] == clab8[ci]);
                        bool self = !offdiag &&
                            (rr8[ri] == warp_n * 32 + nt * 8 + (lane & 3) * 2 + e);
                        if (same) {
                            if (!self) mp[ri] = fmaxf(mp[ri], v);
                        } else {
                            mn[ri] = fminf(mn[ri], v);
                        }
                    }
            }
#pragma unroll
        for (int i = 0; i < 8; i++) {
#pragma unroll
            for (int m = 1; m < 4; m <<= 1) {
                mp[i] = fmaxf(mp[i], __shfl_xor_sync(0xffffffffu, mp[i], m));
                mn[i] = fminf(mn[i], __shfl_xor_sync(0xffffffffu, mn[i], m));
            }
        }
        if ((lane & 3) == 0) {
#pragma unroll
            for (int i = 0; i < 8; i++) {
                if (mp[i] > -2.9e38f) atomicMax(&sMp[rr8[i]], f2i(mp[i]));
                if (mn[i] <  2.9e38f) atomicMin(&sMn[rr8[i]], f2i(mn[i]));
            }
        }

        // --- column-wise mining (off-diagonal only): v' = rn - 2*dot ---
        if (offdiag) {
            float mpc[8], mnc[8];
#pragma unroll
            for (int i = 0; i < 8; i++) { mpc[i] = -3.0e38f; mnc[i] = 3.0e38f; }
#pragma unroll
            for (int nt = 0; nt < 4; nt++)
#pragma unroll
                for (int e = 0; e < 2; e++) {
                    const int ci = nt * 2 + e;
#pragma unroll
                    for (int mt = 0; mt < 4; mt++)
#pragma unroll
                        for (int h = 0; h < 2; h++) {
                            const int ri = mt * 2 + h;
                            float v = fmaf(-2.f, acc[mt][nt][h * 2 + e], rn8[ri]);
                            if (rl8[ri] == clab8[ci]) mpc[ci] = fmaxf(mpc[ci], v);
                            else                       mnc[ci] = fminf(mnc[ci], v);
                        }
                }
#pragma unroll
            for (int i = 0; i < 8; i++) {
#pragma unroll
                for (int m = 4; m < 32; m <<= 1) {
                    mpc[i] = fmaxf(mpc[i], __shfl_xor_sync(0xffffffffu, mpc[i], m));
                    mnc[i] = fminf(mnc[i], __shfl_xor_sync(0xffffffffu, mnc[i], m));
                }
            }
            if (lane < 4) {
#pragma unroll
                for (int nt = 0; nt < 4; nt++)
#pragma unroll
                    for (int e = 0; e < 2; e++) {
                        int cc = warp_n * 32 + nt * 8 + lane * 2 + e;
                        const int ci = nt * 2 + e;
                        if (mpc[ci] > -2.9e38f) atomicMax(&sMp2[cc], f2i(mpc[ci]));
                        if (mnc[ci] <  2.9e38f) atomicMin(&sMn2[cc], f2i(mnc[ci]));
                    }
            }
        }
    }
    __syncthreads();
    if (tid < BM) {
        if (sMp[tid] != INT_MIN) atomicMax(&g_maxpos_i[rowBase + tid], sMp[tid]);
        if (sMn[tid] != INT_MAX) atomicMin(&g_minneg_i[rowBase + tid], sMn[tid]);
        if (offdiag) {
            if (sMp2[tid] != INT_MIN) atomicMax(&g_maxpos_i[colBase + tid], sMp2[tid]);
            if (sMn2[tid] != INT_MAX) atomicMin(&g_minneg_i[colBase + tid], sMn2[tid]);
        }
    }
}

// ---------------------------------------------------------------------------
// Finalize (single block, 1024 threads): per-row sqrt + margin, exact mean
// ---------------------------------------------------------------------------
__global__ void finalize_kernel(float* __restrict__ out) {
    __shared__ float ssum[1024];
    int t = threadIdx.x;
    float s = 0.f;
    for (int r = t; r < N; r += 1024) {
        float rn = g_norms[r];
        int ep = g_maxpos_i[r];
        int en = g_minneg_i[r];
        float ap = (ep == INT_MIN) ? 0.f : sqrtf(fmaxf(rn + i2f(ep), 0.f));
        float an = (en == INT_MAX) ? 1e6f : sqrtf(fmaxf(rn + i2f(en), 0.f));
        s += fmaxf(0.f, 0.3f + ap - an);
    }
    ssum[t] = s;
    __syncthreads();
    for (int off = 512; off > 0; off >>= 1) {
        if (t < off) ssum[t] += ssum[t + off];
        __syncthreads();
    }
    if (t == 0) out[0] = ssum[0] / (float)N;
}

// ---------------------------------------------------------------------------
extern "C" void kernel_launch(void* const* d_in, const int* in_sizes, int n_in,
                              void* d_out, int out_size) {
    const float* feat = (const float*)d_in[0];
    const int* labels = (const int*)d_in[1];
    float* out = (float*)d_out;

    cudaFuncSetAttribute(gram_kernel,
                         cudaFuncAttributeMaxDynamicSharedMemorySize, RING_BYTES);

    prep_kernel<<<(N * 32 + 255) / 256, 256>>>(feat);
    gram_kernel<<<NBLOCKS, THREADS, RING_BYTES>>>(labels);
    finalize_kernel<<<1, 1024>>>(out);
}

// round 15
// speedup vs baseline: 1.2903x; 1.0502x over previous
#include <cuda_runtime.h>
#include <cuda_fp16.h>
#include <cstdint>

#define N 8192
#define D 256
#define KE 256              // pure fp16 hi.hi
#define BM 128
#define BN 128
#define BK 32
#define THREADS 256
#define ITERS (KE / BK)                     // 8
#define NTILE (N / BM)                      // 64
#define NBLOCKS (NTILE * (NTILE + 1) / 2)   // 2080
#define NSTAGE 4
#define LDA 40
#define A_BYTES (BM * LDA * 2)              // 10240
#define B_BYTES (BN * LDA * 2)              // 10240
#define STAGE_BYTES (A_BYTES + B_BYTES)     // 20480
#define RING_BYTES (NSTAGE * STAGE_BYTES)   // 81920

// ---------------------------------------------------------------------------
__device__ __half g_hi[N * D];
__device__ float g_norms[N];
__device__ int   g_maxpos_i[N];          // encoded floats, INT_MIN = none
__device__ int   g_minneg_i[N];          // encoded floats, INT_MAX = none

__device__ __forceinline__ int f2i(float f) {
    int i = __float_as_int(f);
    return i >= 0 ? i : (i ^ 0x7fffffff);
}
__device__ __forceinline__ float i2f(int i) {
    return __int_as_float(i >= 0 ? i : (i ^ 0x7fffffff));
}
__device__ __forceinline__ uint32_t smem_u32(const void* p) {
    uint32_t a;
    asm("{ .reg .u64 t; cvta.to.shared.u64 t, %1; cvt.u32.u64 %0, t; }"
        : "=r"(a) : "l"(p));
    return a;
}
__device__ __forceinline__ void cp16(uint32_t s, const void* g) {
    asm volatile("cp.async.cg.shared.global [%0], [%1], 16;\n"
                 :: "r"(s), "l"(g) : "memory");
}
#define CP_COMMIT() asm volatile("cp.async.commit_group;" ::: "memory")
#define CP_WAIT(n)  asm volatile("cp.async.wait_group %0;" :: "n"(n) : "memory")

#define LDSM_X4(r0, r1, r2, r3, a)                                            \
    asm volatile("ldmatrix.sync.aligned.m8n8.x4.shared.b16 {%0,%1,%2,%3}, [%4];" \
                 : "=r"(r0), "=r"(r1), "=r"(r2), "=r"(r3) : "r"(a))

#define MMA_F16(c, a0, a1, a2, a3, b0, b1)                                    \
    asm volatile(                                                             \
        "mma.sync.aligned.m16n8k16.row.col.f32.f16.f16.f32 "                  \
        "{%0,%1,%2,%3}, {%4,%5,%6,%7}, {%8,%9}, {%0,%1,%2,%3};"               \
        : "+f"((c)[0]), "+f"((c)[1]), "+f"((c)[2]), "+f"((c)[3])              \
        : "r"(a0), "r"(a1), "r"(a2), "r"(a3), "r"(b0), "r"(b1))

// ---------------------------------------------------------------------------
// Prep (fused): warp per row — fp16 convert + exact fp32 norm + init
// ---------------------------------------------------------------------------
__global__ void prep_kernel(const float* __restrict__ feat) {
    int gtid = blockIdx.x * blockDim.x + threadIdx.x;
    int row = gtid >> 5;
    int lane = gtid & 31;
    if (row >= N) return;
    const float4* f = reinterpret_cast<const float4*>(feat + (size_t)row * D);
    float4 v0 = f[lane * 2];
    float4 v1 = f[lane * 2 + 1];
    float s = v0.x * v0.x + v0.y * v0.y + v0.z * v0.z + v0.w * v0.w
            + v1.x * v1.x + v1.y * v1.y + v1.z * v1.z + v1.w * v1.w;
    __half h[8];
    h[0] = __float2half_rn(v0.x); h[1] = __float2half_rn(v0.y);
    h[2] = __float2half_rn(v0.z); h[3] = __float2half_rn(v0.w);
    h[4] = __float2half_rn(v1.x); h[5] = __float2half_rn(v1.y);
    h[6] = __float2half_rn(v1.z); h[7] = __float2half_rn(v1.w);
    *reinterpret_cast<uint4*>(g_hi + (size_t)row * D + lane * 8) =
        *reinterpret_cast<uint4*>(h);
#pragma unroll
    for (int m = 16; m > 0; m >>= 1) s += __shfl_xor_sync(0xffffffffu, s, m);
    if (lane == 0) {
        g_norms[row] = s;
        g_maxpos_i[row] = INT_MIN;
        g_minneg_i[row] = INT_MAX;
    }
}

// ---------------------------------------------------------------------------
// Main: symmetric HMMA Gram (128x128, occ 2), 4-stage ring, 1 sync/iter,
// atomic-free deterministic epilogue reduction.
// ---------------------------------------------------------------------------
__global__ __launch_bounds__(THREADS, 2)
void gram_kernel(const int* __restrict__ labels) {
    extern __shared__ char ring[];
    __shared__ int   sColLab[BN];
    __shared__ float sColNorm[BN];
    __shared__ int   sRowLab[BM];
    __shared__ float sRowNorm[BM];
    __shared__ float sMpW[4][BM], sMnW[4][BM];   // per-warp_n row results
    __shared__ float sMpC[2][BN], sMnC[2][BN];   // per-warp_m col results

    // decode upper-triangular tile pair (I <= J)
    int t = blockIdx.x;
    int I = 0;
    while (t >= NTILE - I) { t -= NTILE - I; I++; }
    const int J = I + t;
    const bool offdiag = (I != J);
    const int rowBase = I * BM;
    const int colBase = J * BN;

    const int tid = threadIdx.x;
    const int lane = tid & 31;
    const int wid = tid >> 5;
    const int warp_m = wid >> 2;          // 0..1  (64 rows each)
    const int warp_n = wid & 3;           // 0..3  (32 cols each)

    if (tid < BM) {
        sColLab[tid]  = labels[colBase + tid];
        sColNorm[tid] = g_norms[colBase + tid];
        sRowLab[tid]  = labels[rowBase + tid];
        sRowNorm[tid] = g_norms[rowBase + tid];
    }

    const uint32_t ringBase = smem_u32(ring);
    const uint32_t aOff = ((warp_m * 64 + (lane & 15)) * LDA + (lane >> 4) * 8) * 2;
    const uint32_t bOff = ((warp_n * 32 + (lane & 7) + ((lane >> 4) & 1) * 8) * LDA
                          + ((lane >> 3) & 1) * 8) * 2;

    const __half* ga = g_hi + (size_t)rowBase * D;
    const __half* gb = g_hi + (size_t)colBase * D;

    auto load_stage = [&](int kt, int stg) {
        const uint32_t sA = ringBase + stg * STAGE_BYTES;
        const uint32_t sB = sA + A_BYTES;
        const int k0 = kt * BK;
#pragma unroll
        for (int i = 0; i < 2; i++) {
            int idx = tid + i * THREADS;
            int r = idx >> 2, c = idx & 3;
            cp16(sA + (r * LDA + c * 8) * 2, ga + (size_t)r * D + k0 + c * 8);
        }
#pragma unroll
        for (int i = 0; i < 2; i++) {
            int idx = tid + i * THREADS;
            int r = idx >> 2, c = idx & 3;
            cp16(sB + (r * LDA + c * 8) * 2, gb + (size_t)r * D + k0 + c * 8);
        }
        CP_COMMIT();
    };

    float acc[4][4][4];
#pragma unroll
    for (int i = 0; i < 4; i++)
#pragma unroll
        for (int j = 0; j < 4; j++)
#pragma unroll
            for (int e = 0; e < 4; e++) acc[i][j][e] = 0.f;

    load_stage(0, 0);
    load_stage(1, 1);
    load_stage(2, 2);

    for (int it = 0; it < ITERS; ++it) {
        CP_WAIT(2);
        __syncthreads();
        // slot (it+3)&3's last readers ran in iter it-1; all passed the sync
        if (it + 3 < ITERS) load_stage(it + 3, (it + 3) & (NSTAGE - 1));
        else CP_COMMIT();   // empty group keeps wait_group accounting exact

        const uint32_t sA = ringBase + (it & (NSTAGE - 1)) * STAGE_BYTES;
        const uint32_t sB = sA + A_BYTES;
#pragma unroll
        for (int ks = 0; ks < 2; ks++) {
            uint32_t aF[4][4], bF[2][4];
#pragma unroll
            for (int mt = 0; mt < 4; mt++)
                LDSM_X4(aF[mt][0], aF[mt][1], aF[mt][2], aF[mt][3],
                        sA + aOff + mt * (16 * LDA * 2) + ks * 32);
#pragma unroll
            for (int ng = 0; ng < 2; ng++)
                LDSM_X4(bF[ng][0], bF[ng][1], bF[ng][2], bF[ng][3],
                        sB + bOff + ng * (16 * LDA * 2) + ks * 32);
#pragma unroll
            for (int mt = 0; mt < 4; mt++) {
#pragma unroll
                for (int nt = 0; nt < 4; nt++) {
                    const int ng = nt >> 1;
                    const int hi = (nt & 1) << 1;
                    MMA_F16(acc[mt][nt], aF[mt][0], aF[mt][1], aF[mt][2],
                            aF[mt][3], bF[ng][hi], bF[ng][hi + 1]);
                }
            }
        }
    }

    // ---- epilogue: atomic-free two-phase mining reduction ----
    {
        float cn8[8]; int clab8[8];
#pragma unroll
        for (int nt = 0; nt < 4; nt++)
#pragma unroll
            for (int e = 0; e < 2; e++) {
                int cc = warp_n * 32 + nt * 8 + (lane & 3) * 2 + e;
                cn8[nt * 2 + e] = sColNorm[cc];
                clab8[nt * 2 + e] = sColLab[cc];
            }
        int rl8[8]; float rn8[8]; int rr8[8];
#pragma unroll
        for (int mt = 0; mt < 4; mt++)
#pragma unroll
            for (int h = 0; h < 2; h++) {
                int rr = warp_m * 64 + mt * 16 + (lane >> 2) + h * 8;
                rr8[mt * 2 + h] = rr;
                rl8[mt * 2 + h] = sRowLab[rr];
                rn8[mt * 2 + h] = sRowNorm[rr];
            }

        // --- row-wise mining: v = cn - 2*dot ---
        float mp[8], mn[8];
#pragma unroll
        for (int i = 0; i < 8; i++) { mp[i] = -3.0e38f; mn[i] = 3.0e38f; }
#pragma unroll
        for (int mt = 0; mt < 4; mt++)
#pragma unroll
            for (int h = 0; h < 2; h++) {
                const int ri = mt * 2 + h;
#pragma unroll
                for (int nt = 0; nt < 4; nt++)
#pragma unroll
                    for (int e = 0; e < 2; e++) {
                        const int ci = nt * 2 + e;
                        float v = fmaf(-2.f, acc[mt][nt][h * 2 + e], cn8[ci]);
                        bool same = (rl8[ri] == clab8[ci]);
                        bool self = !offdiag &&
                            (rr8[ri] == warp_n * 32 + nt * 8 + (lane & 3) * 2 + e);
                        if (same) {
                            if (!self) mp[ri] = fmaxf(mp[ri], v);
                        } else {
                            mn[ri] = fminf(mn[ri], v);
                        }
                    }
            }
#pragma unroll
        for (int i = 0; i < 8; i++) {
#pragma unroll
            for (int m = 1; m < 4; m <<= 1) {
                mp[i] = fmaxf(mp[i], __shfl_xor_sync(0xffffffffu, mp[i], m));
                mn[i] = fminf(mn[i], __shfl_xor_sync(0xffffffffu, mn[i], m));
            }
        }
        if ((lane & 3) == 0) {
#pragma unroll
            for (int i = 0; i < 8; i++) {
                sMpW[warp_n][rr8[i]] = mp[i];    // lane-consecutive rows: no conflict
                sMnW[warp_n][rr8[i]] = mn[i];
            }
        }

        // --- column-wise mining (off-diagonal only): v' = rn - 2*dot ---
        if (offdiag) {
            float mpc[8], mnc[8];
#pragma unroll
            for (int i = 0; i < 8; i++) { mpc[i] = -3.0e38f; mnc[i] = 3.0e38f; }
#pragma unroll
            for (int nt = 0; nt < 4; nt++)
#pragma unroll
                for (int e = 0; e < 2; e++) {
                    const int ci = nt * 2 + e;
#pragma unroll
                    for (int mt = 0; mt < 4; mt++)
#pragma unroll
                        for (int h = 0; h < 2; h++) {
                            const int ri = mt * 2 + h;
                            float v = fmaf(-2.f, acc[mt][nt][h * 2 + e], rn8[ri]);
                            if (rl8[ri] == clab8[ci]) mpc[ci] = fmaxf(mpc[ci], v);
                            else                       mnc[ci] = fminf(mnc[ci], v);
                        }
                }
#pragma unroll
            for (int i = 0; i < 8; i++) {
#pragma unroll
                for (int m = 4; m < 32; m <<= 1) {
                    mpc[i] = fmaxf(mpc[i], __shfl_xor_sync(0xffffffffu, mpc[i], m));
                    mnc[i] = fminf(mnc[i], __shfl_xor_sync(0xffffffffu, mnc[i], m));
                }
            }
            if (lane < 4) {
#pragma unroll
                for (int nt = 0; nt < 4; nt++)
#pragma unroll
                    for (int e = 0; e < 2; e++) {
                        int cc = warp_n * 32 + nt * 8 + lane * 2 + e;
                        const int ci = nt * 2 + e;
                        sMpC[warp_m][cc] = mpc[ci];
                        sMnC[warp_m][cc] = mnc[ci];
                    }
            }
        }
    }
    __syncthreads();
    // final fold + global publish (128 threads; atomics only to global)
    if (tid < BM) {
        float mp = fmaxf(fmaxf(sMpW[0][tid], sMpW[1][tid]),
                         fmaxf(sMpW[2][tid], sMpW[3][tid]));
        float mn = fminf(fminf(sMnW[0][tid], sMnW[1][tid]),
                         fminf(sMnW[2][tid], sMnW[3][tid]));
        if (mp > -2.9e38f) atomicMax(&g_maxpos_i[rowBase + tid], f2i(mp));
        if (mn <  2.9e38f) atomicMin(&g_minneg_i[rowBase + tid], f2i(mn));
        if (offdiag) {
            float mpc = fmaxf(sMpC[0][tid], sMpC[1][tid]);
            float mnc = fminf(sMnC[0][tid], sMnC[1][tid]);
            if (mpc > -2.9e38f) atomicMax(&g_maxpos_i[colBase + tid], f2i(mpc));
            if (mnc <  2.9e38f) atomicMin(&g_minneg_i[colBase + tid], f2i(mnc));
        }
    }
}

// ---------------------------------------------------------------------------
// Finalize (single block, 1024 threads): per-row sqrt + margin, exact mean
// ---------------------------------------------------------------------------
__global__ void finalize_kernel(float* __restrict__ out) {
    __shared__ float ssum[1024];
    int t = threadIdx.x;
    float s = 0.f;
    for (int r = t; r < N; r += 1024) {
        float rn = g_norms[r];
        int ep = g_maxpos_i[r];
        int en = g_minneg_i[r];
        float ap = (ep == INT_MIN) ? 0.f : sqrtf(fmaxf(rn + i2f(ep), 0.f));
        float an = (en == INT_MAX) ? 1e6f : sqrtf(fmaxf(rn + i2f(en), 0.f));
        s += fmaxf(0.f, 0.3f + ap - an);
    }
    ssum[t] = s;
    __syncthreads();
    for (int off = 512; off > 0; off >>= 1) {
        if (t < off) ssum[t] += ssum[t + off];
        __syncthreads();
    }
    if (t == 0) out[0] = ssum[0] / (float)N;
}

// ---------------------------------------------------------------------------
extern "C" void kernel_launch(void* const* d_in, const int* in_sizes, int n_in,
                              void* d_out, int out_size) {
    const float* feat = (const float*)d_in[0];
    const int* labels = (const int*)d_in[1];
    float* out = (float*)d_out;

    cudaFuncSetAttribute(gram_kernel,
                         cudaFuncAttributeMaxDynamicSharedMemorySize, RING_BYTES);

    prep_kernel<<<(N * 32 + 255) / 256, 256>>>(feat);
    gram_kernel<<<NBLOCKS, THREADS, RING_BYTES>>>(labels);
    finalize_kernel<<<1, 1024>>>(out);
}